// round 5
// baseline (speedup 1.0000x reference)
#include <cuda_runtime.h>
#include <math.h>

#define BATCH 8
#define TLEN 4096
#define DK 16
#define DV 64
// sigmoid(w - d) underflows to exactly 0.0f in fp32 for d >= 160 -> band is EXACT.
#define WIN 160
#define TQ 128                  // queries per CTA
#define KW (TQ + WIN)           // 288 key rows per CTA
#define KS 16                   // K smem row stride (floats)
#define VS 68                   // V smem row stride (floats, 16B-aligned rows)
#define NTHREADS 256            // 2 threads per query (band halves)
#define HALF_WIN 80
#define CAP 20                  // survivor list capacity per thread (mean ~3; overflow -> exact fallback)

__global__ __launch_bounds__(NTHREADS, 2)
void screening_kernel(const float* __restrict__ qg,
                      const float* __restrict__ kg,
                      const float* __restrict__ vg,
                      const float* __restrict__ s_r,
                      const float* __restrict__ s_w,
                      float* __restrict__ out)
{
    extern __shared__ float sm[];
    float* sig_sm = sm;                      // [WIN]
    float* k_sm   = sm + WIN;                // [KW * KS]
    float* v_sm   = k_sm + KW * KS;          // [KW * VS] (reused as reduction buffer)

    const int tid  = threadIdx.x;
    const int qi   = tid & (TQ - 1);         // query within tile
    const int half = tid >> 7;               // 0: d in [0,80), 1: d in [80,160)
    const int q0   = blockIdx.x * TQ;
    const int b    = blockIdx.y;
    const int kstart = q0 - (WIN - 1);

    const float r = expf(s_r[0]) + 1.0f;
    const float w = expf(s_w[0]) + 1.0f;

    if (tid < WIN) {
        float x = w - (float)tid;
        sig_sm[tid] = 1.0f / (1.0f + expf(-x));
    }

    // ---- Load + L2-normalize K window: one thread per row ----
    for (int row = tid; row < KW; row += NTHREADS) {
        const int j = kstart + row;
        float4 a0, a1, a2, a3;
        if (j >= 0) {
            const float4* gp = reinterpret_cast<const float4*>(kg + ((size_t)b * TLEN + j) * DK);
            a0 = gp[0]; a1 = gp[1]; a2 = gp[2]; a3 = gp[3];
        } else {
            a0 = a1 = a2 = a3 = make_float4(0.f, 0.f, 0.f, 0.f);
        }
        float ss = a0.x*a0.x + a0.y*a0.y + a0.z*a0.z + a0.w*a0.w
                 + a1.x*a1.x + a1.y*a1.y + a1.z*a1.z + a1.w*a1.w
                 + a2.x*a2.x + a2.y*a2.y + a2.z*a2.z + a2.w*a2.w
                 + a3.x*a3.x + a3.y*a3.y + a3.z*a3.z + a3.w*a3.w;
        const float inv = 1.0f / fmaxf(sqrtf(ss), 1e-12f);
        float4* dst = reinterpret_cast<float4*>(k_sm + row * KS);
        dst[0] = make_float4(a0.x*inv, a0.y*inv, a0.z*inv, a0.w*inv);
        dst[1] = make_float4(a1.x*inv, a1.y*inv, a1.z*inv, a1.w*inv);
        dst[2] = make_float4(a2.x*inv, a2.y*inv, a2.z*inv, a2.w*inv);
        dst[3] = make_float4(a3.x*inv, a3.y*inv, a3.z*inv, a3.w*inv);
    }

    // ---- Load + L2-normalize V window: 16-lane groups, one float4 per lane ----
    {
        const int g = tid >> 4;              // 16 groups
        const int l = tid & 15;
        for (int row = g; row < KW; row += NTHREADS / 16) {   // 18 uniform iters
            const int j = kstart + row;
            float4 x = make_float4(0.f, 0.f, 0.f, 0.f);
            if (j >= 0)
                x = reinterpret_cast<const float4*>(vg + ((size_t)b * TLEN + j) * DV)[l];
            float ss = x.x*x.x + x.y*x.y + x.z*x.z + x.w*x.w;
            #pragma unroll
            for (int m = 8; m >= 1; m >>= 1)
                ss += __shfl_xor_sync(0xffffffffu, ss, m);
            const float inv = 1.0f / fmaxf(sqrtf(ss), 1e-12f);
            float4* dst = reinterpret_cast<float4*>(v_sm + row * VS + l * 4);
            *dst = make_float4(x.x*inv, x.y*inv, x.z*inv, x.w*inv);
        }
    }

    __syncthreads();

    // ---- Per-thread query (normalized, 16 registers) ----
    const int i = q0 + qi;
    float4 q0v, q1v, q2v, q3v;
    {
        const float4* gp = reinterpret_cast<const float4*>(qg + ((size_t)b * TLEN + i) * DK);
        q0v = gp[0]; q1v = gp[1]; q2v = gp[2]; q3v = gp[3];
        float ss = q0v.x*q0v.x + q0v.y*q0v.y + q0v.z*q0v.z + q0v.w*q0v.w
                 + q1v.x*q1v.x + q1v.y*q1v.y + q1v.z*q1v.z + q1v.w*q1v.w
                 + q2v.x*q2v.x + q2v.y*q2v.y + q2v.z*q2v.z + q2v.w*q2v.w
                 + q3v.x*q3v.x + q3v.y*q3v.y + q3v.z*q3v.z + q3v.w*q3v.w;
        const float inv = 1.0f / fmaxf(sqrtf(ss), 1e-12f);
        q0v.x*=inv; q0v.y*=inv; q0v.z*=inv; q0v.w*=inv;
        q1v.x*=inv; q1v.y*=inv; q1v.z*=inv; q1v.w*=inv;
        q2v.x*=inv; q2v.y*=inv; q2v.z*=inv; q2v.w*=inv;
        q3v.x*=inv; q3v.y*=inv; q3v.z*=inv; q3v.w*=inv;
    }

    float acc[DV];
    #pragma unroll
    for (int c = 0; c < DV; ++c) acc[c] = 0.0f;

    const float one_minus_r = 1.0f - r;
    const int dmax = (i < WIN - 1) ? i : (WIN - 1);
    const int d0 = half * HALF_WIN;
    const int d1 = (dmax < d0 + HALF_WIN - 1) ? dmax : (d0 + HALF_WIN - 1);

    // ---- Pass 1: score all band steps, compact survivors (local-memory list) ----
    float         al_list[CAP];
    unsigned char d_list[CAP];
    int cnt = 0;

    #pragma unroll 2
    for (int d = d0; d <= d1; ++d) {
        const int jj = qi + (WIN - 1) - d;               // smem row of key j = i - d
        const float4* kr = reinterpret_cast<const float4*>(k_sm + jj * KS);
        float4 k0 = kr[0], k1 = kr[1], k2 = kr[2], k3 = kr[3];
        float s0 = q0v.x*k0.x; s0 = fmaf(q0v.y,k0.y,s0); s0 = fmaf(q0v.z,k0.z,s0); s0 = fmaf(q0v.w,k0.w,s0);
        float s1 = q1v.x*k1.x; s1 = fmaf(q1v.y,k1.y,s1); s1 = fmaf(q1v.z,k1.z,s1); s1 = fmaf(q1v.w,k1.w,s1);
        float s2 = q2v.x*k2.x; s2 = fmaf(q2v.y,k2.y,s2); s2 = fmaf(q2v.z,k2.z,s2); s2 = fmaf(q2v.w,k2.w,s2);
        float s3 = q3v.x*k3.x; s3 = fmaf(q3v.y,k3.y,s3); s3 = fmaf(q3v.z,k3.z,s3); s3 = fmaf(q3v.w,k3.w,s3);
        const float s = (s0 + s1) + (s2 + s3);
        const float a = fmaxf(fmaf(r, s, one_minus_r), 0.0f);   // relu(1 - r(1-s))
        if (a > 0.0f) {
            const float al = a * a * sig_sm[d];
            if (cnt < CAP) {                          // push (almost always)
                al_list[cnt] = al;
                d_list[cnt]  = (unsigned char)d;
                ++cnt;
            } else {                                  // exact fallback: accumulate now
                const float4* vr = reinterpret_cast<const float4*>(v_sm + jj * VS);
                #pragma unroll
                for (int c4 = 0; c4 < DV / 4; ++c4) {
                    float4 vv = vr[c4];
                    acc[4*c4+0] = fmaf(al, vv.x, acc[4*c4+0]);
                    acc[4*c4+1] = fmaf(al, vv.y, acc[4*c4+1]);
                    acc[4*c4+2] = fmaf(al, vv.z, acc[4*c4+2]);
                    acc[4*c4+3] = fmaf(al, vv.w, acc[4*c4+3]);
                }
            }
        }
    }

    // ---- Pass 2: drain survivor list (trip = max over warp ~ 8, not 58) ----
    #pragma unroll 1
    for (int e = 0; e < cnt; ++e) {
        const float al = al_list[e];
        const int   d  = (int)d_list[e];
        const int   jj = qi + (WIN - 1) - d;
        const float4* vr = reinterpret_cast<const float4*>(v_sm + jj * VS);
        #pragma unroll
        for (int c4 = 0; c4 < DV / 4; ++c4) {
            float4 vv = vr[c4];
            acc[4*c4+0] = fmaf(al, vv.x, acc[4*c4+0]);
            acc[4*c4+1] = fmaf(al, vv.y, acc[4*c4+1]);
            acc[4*c4+2] = fmaf(al, vv.z, acc[4*c4+2]);
            acc[4*c4+3] = fmaf(al, vv.w, acc[4*c4+3]);
        }
    }

    // ---- Cross-half reduction through smem (v_sm reusable after pass 2) ----
    __syncthreads();
    float* red = v_sm;
    if (half == 1) {
        float4* dst = reinterpret_cast<float4*>(red + qi * VS);
        #pragma unroll
        for (int c4 = 0; c4 < DV / 4; ++c4)
            dst[c4] = make_float4(acc[4*c4+0], acc[4*c4+1], acc[4*c4+2], acc[4*c4+3]);
    }
    __syncthreads();
    if (half == 0) {
        const float4* src = reinterpret_cast<const float4*>(red + qi * VS);
        #pragma unroll
        for (int c4 = 0; c4 < DV / 4; ++c4) {
            float4 p = src[c4];
            acc[4*c4+0] += p.x; acc[4*c4+1] += p.y;
            acc[4*c4+2] += p.z; acc[4*c4+3] += p.w;
        }

        // ---- TanhNorm epilogue ----
        float ss = 0.0f;
        #pragma unroll
        for (int c = 0; c < DV; ++c) ss = fmaf(acc[c], acc[c], ss);
        const float hn = fmaxf(sqrtf(ss), 1e-8f);
        const float scale = tanhf(hn) / hn;

        float4* op = reinterpret_cast<float4*>(out + ((size_t)b * TLEN + i) * DV);
        #pragma unroll
        for (int c4 = 0; c4 < DV / 4; ++c4)
            op[c4] = make_float4(acc[4*c4+0]*scale, acc[4*c4+1]*scale,
                                 acc[4*c4+2]*scale, acc[4*c4+3]*scale);
    }
}

extern "C" void kernel_launch(void* const* d_in, const int* in_sizes, int n_in,
                              void* d_out, int out_size)
{
    const float* q   = (const float*)d_in[0];
    const float* k   = (const float*)d_in[1];
    const float* v   = (const float*)d_in[2];
    const float* s_r = (const float*)d_in[3];
    const float* s_w = (const float*)d_in[4];
    float* out = (float*)d_out;

    const size_t smem = (size_t)(WIN + KW * KS + KW * VS) * sizeof(float); // ~97.4 KB
    cudaFuncSetAttribute(screening_kernel, cudaFuncAttributeMaxDynamicSharedMemorySize, (int)smem);

    dim3 grid(TLEN / TQ, BATCH);
    screening_kernel<<<grid, NTHREADS, smem>>>(q, k, v, s_r, s_w, out);
}

// round 6
// speedup vs baseline: 2.0020x; 2.0020x over previous
#include <cuda_runtime.h>
#include <math.h>

#define BATCH 8
#define TLEN 4096
#define DK 16
#define DV 64
// sigmoid(w - d) underflows to exactly 0.0f in fp32 for d >= 160 -> band is EXACT.
#define WIN 160
#define TQ 128                  // queries per CTA
#define KW (TQ + WIN)           // 288 key rows per CTA
#define KS 20                   // K smem row stride (floats): LDS.128 conflict-free in hot loop
#define VS 68                   // V smem row stride (floats, 16B-aligned rows)
#define NTHREADS 256            // 2 threads per query (band halves)
#define HALF_WIN 80
#define CAP 10                  // survivor list capacity per thread (mean ~3; overflow -> exact fallback)
#define LSTRIDE 11              // per-thread list stride in words (odd -> conflict-free)

__global__ __launch_bounds__(NTHREADS, 2)
void screening_kernel(const float* __restrict__ qg,
                      const float* __restrict__ kg,
                      const float* __restrict__ vg,
                      const float* __restrict__ s_r,
                      const float* __restrict__ s_w,
                      float* __restrict__ out)
{
    extern __shared__ float sm[];
    float* sig_sm = sm;                               // [WIN]
    float* k_sm   = sm + WIN;                         // [KW * KS]
    float* v_sm   = k_sm + KW * KS;                   // [KW * VS] (reused as reduction buffer)
    unsigned* list_sm = reinterpret_cast<unsigned*>(v_sm + KW * VS);  // [NTHREADS * LSTRIDE]

    const int tid  = threadIdx.x;
    const int qi   = tid & (TQ - 1);         // query within tile
    const int half = tid >> 7;               // 0: d in [0,80), 1: d in [80,160)
    const int q0   = blockIdx.x * TQ;
    const int b    = blockIdx.y;
    const int kstart = q0 - (WIN - 1);
    unsigned* mylist = list_sm + tid * LSTRIDE;

    const float r = expf(s_r[0]) + 1.0f;
    const float w = expf(s_w[0]) + 1.0f;

    if (tid < WIN) {
        float x = w - (float)tid;
        sig_sm[tid] = 1.0f / (1.0f + expf(-x));
    }

    // ---- Load + L2-normalize K window: one thread per row ----
    for (int row = tid; row < KW; row += NTHREADS) {
        const int j = kstart + row;
        float4 a0, a1, a2, a3;
        if (j >= 0) {
            const float4* gp = reinterpret_cast<const float4*>(kg + ((size_t)b * TLEN + j) * DK);
            a0 = gp[0]; a1 = gp[1]; a2 = gp[2]; a3 = gp[3];
        } else {
            a0 = a1 = a2 = a3 = make_float4(0.f, 0.f, 0.f, 0.f);
        }
        float ss = a0.x*a0.x + a0.y*a0.y + a0.z*a0.z + a0.w*a0.w
                 + a1.x*a1.x + a1.y*a1.y + a1.z*a1.z + a1.w*a1.w
                 + a2.x*a2.x + a2.y*a2.y + a2.z*a2.z + a2.w*a2.w
                 + a3.x*a3.x + a3.y*a3.y + a3.z*a3.z + a3.w*a3.w;
        const float inv = 1.0f / fmaxf(sqrtf(ss), 1e-12f);
        float4* dst = reinterpret_cast<float4*>(k_sm + row * KS);
        dst[0] = make_float4(a0.x*inv, a0.y*inv, a0.z*inv, a0.w*inv);
        dst[1] = make_float4(a1.x*inv, a1.y*inv, a1.z*inv, a1.w*inv);
        dst[2] = make_float4(a2.x*inv, a2.y*inv, a2.z*inv, a2.w*inv);
        dst[3] = make_float4(a3.x*inv, a3.y*inv, a3.z*inv, a3.w*inv);
    }

    // ---- Load + L2-normalize V window: 16-lane groups, one float4 per lane ----
    {
        const int g = tid >> 4;              // 16 groups
        const int l = tid & 15;
        for (int row = g; row < KW; row += NTHREADS / 16) {   // 18 uniform iters
            const int j = kstart + row;
            float4 x = make_float4(0.f, 0.f, 0.f, 0.f);
            if (j >= 0)
                x = reinterpret_cast<const float4*>(vg + ((size_t)b * TLEN + j) * DV)[l];
            float ss = x.x*x.x + x.y*x.y + x.z*x.z + x.w*x.w;
            #pragma unroll
            for (int m = 8; m >= 1; m >>= 1)
                ss += __shfl_xor_sync(0xffffffffu, ss, m);
            const float inv = 1.0f / fmaxf(sqrtf(ss), 1e-12f);
            float4* dst = reinterpret_cast<float4*>(v_sm + row * VS + l * 4);
            *dst = make_float4(x.x*inv, x.y*inv, x.z*inv, x.w*inv);
        }
    }

    __syncthreads();

    // ---- Per-thread query (normalized, 16 registers) ----
    const int i = q0 + qi;
    float4 q0v, q1v, q2v, q3v;
    {
        const float4* gp = reinterpret_cast<const float4*>(qg + ((size_t)b * TLEN + i) * DK);
        q0v = gp[0]; q1v = gp[1]; q2v = gp[2]; q3v = gp[3];
        float ss = q0v.x*q0v.x + q0v.y*q0v.y + q0v.z*q0v.z + q0v.w*q0v.w
                 + q1v.x*q1v.x + q1v.y*q1v.y + q1v.z*q1v.z + q1v.w*q1v.w
                 + q2v.x*q2v.x + q2v.y*q2v.y + q2v.z*q2v.z + q2v.w*q2v.w
                 + q3v.x*q3v.x + q3v.y*q3v.y + q3v.z*q3v.z + q3v.w*q3v.w;
        const float inv = 1.0f / fmaxf(sqrtf(ss), 1e-12f);
        q0v.x*=inv; q0v.y*=inv; q0v.z*=inv; q0v.w*=inv;
        q1v.x*=inv; q1v.y*=inv; q1v.z*=inv; q1v.w*=inv;
        q2v.x*=inv; q2v.y*=inv; q2v.z*=inv; q2v.w*=inv;
        q3v.x*=inv; q3v.y*=inv; q3v.z*=inv; q3v.w*=inv;
    }

    float acc[DV];
    #pragma unroll
    for (int c = 0; c < DV; ++c) acc[c] = 0.0f;

    const float one_minus_r = 1.0f - r;
    const int dmax = (i < WIN - 1) ? i : (WIN - 1);
    const int d0 = half * HALF_WIN;
    const int d1 = (dmax < d0 + HALF_WIN - 1) ? dmax : (d0 + HALF_WIN - 1);

    // ---- Pass 1: score all band steps; pack survivors (alpha|d) into smem list ----
    int cnt = 0;

    #pragma unroll 2
    for (int d = d0; d <= d1; ++d) {
        const int jj = qi + (WIN - 1) - d;               // smem row of key j = i - d
        const float4* kr = reinterpret_cast<const float4*>(k_sm + jj * KS);
        float4 k0 = kr[0], k1 = kr[1], k2 = kr[2], k3 = kr[3];
        float s0 = q0v.x*k0.x; s0 = fmaf(q0v.y,k0.y,s0); s0 = fmaf(q0v.z,k0.z,s0); s0 = fmaf(q0v.w,k0.w,s0);
        float s1 = q1v.x*k1.x; s1 = fmaf(q1v.y,k1.y,s1); s1 = fmaf(q1v.z,k1.z,s1); s1 = fmaf(q1v.w,k1.w,s1);
        float s2 = q2v.x*k2.x; s2 = fmaf(q2v.y,k2.y,s2); s2 = fmaf(q2v.z,k2.z,s2); s2 = fmaf(q2v.w,k2.w,s2);
        float s3 = q3v.x*k3.x; s3 = fmaf(q3v.y,k3.y,s3); s3 = fmaf(q3v.z,k3.z,s3); s3 = fmaf(q3v.w,k3.w,s3);
        const float s = (s0 + s1) + (s2 + s3);
        const float a = fmaxf(fmaf(r, s, one_minus_r), 0.0f);   // relu(1 - r(1-s))
        if (a > 0.0f) {
            const float al = a * a * sig_sm[d];
            if (cnt < CAP) {
                // pack: alpha fp32 bits, low 8 mantissa bits replaced by d (<=1.5e-5 rel err)
                mylist[cnt] = (__float_as_uint(al) & 0xFFFFFF00u) | (unsigned)d;
                ++cnt;
            } else {                                  // exact fallback (rare): accumulate now
                const float4* vr = reinterpret_cast<const float4*>(v_sm + jj * VS);
                #pragma unroll
                for (int c4 = 0; c4 < DV / 4; ++c4) {
                    float4 vv = vr[c4];
                    acc[4*c4+0] = fmaf(al, vv.x, acc[4*c4+0]);
                    acc[4*c4+1] = fmaf(al, vv.y, acc[4*c4+1]);
                    acc[4*c4+2] = fmaf(al, vv.z, acc[4*c4+2]);
                    acc[4*c4+3] = fmaf(al, vv.w, acc[4*c4+3]);
                }
            }
        }
    }

    // ---- Pass 2: drain survivor list (warp trip = max over lanes ~ 7-8, not ~38) ----
    #pragma unroll 1
    for (int e = 0; e < cnt; ++e) {
        const unsigned u = mylist[e];
        const int   d  = (int)(u & 0xFFu);
        const float al = __uint_as_float(u & 0xFFFFFF00u);
        const int   jj = qi + (WIN - 1) - d;
        const float4* vr = reinterpret_cast<const float4*>(v_sm + jj * VS);
        #pragma unroll
        for (int c4 = 0; c4 < DV / 4; ++c4) {
            float4 vv = vr[c4];
            acc[4*c4+0] = fmaf(al, vv.x, acc[4*c4+0]);
            acc[4*c4+1] = fmaf(al, vv.y, acc[4*c4+1]);
            acc[4*c4+2] = fmaf(al, vv.z, acc[4*c4+2]);
            acc[4*c4+3] = fmaf(al, vv.w, acc[4*c4+3]);
        }
    }

    // ---- Cross-half reduction through smem (v_sm reusable after pass 2) ----
    __syncthreads();
    float* red = v_sm;
    if (half == 1) {
        float4* dst = reinterpret_cast<float4*>(red + qi * VS);
        #pragma unroll
        for (int c4 = 0; c4 < DV / 4; ++c4)
            dst[c4] = make_float4(acc[4*c4+0], acc[4*c4+1], acc[4*c4+2], acc[4*c4+3]);
    }
    __syncthreads();
    if (half == 0) {
        const float4* src = reinterpret_cast<const float4*>(red + qi * VS);
        #pragma unroll
        for (int c4 = 0; c4 < DV / 4; ++c4) {
            float4 p = src[c4];
            acc[4*c4+0] += p.x; acc[4*c4+1] += p.y;
            acc[4*c4+2] += p.z; acc[4*c4+3] += p.w;
        }

        // ---- TanhNorm epilogue ----
        float ss = 0.0f;
        #pragma unroll
        for (int c = 0; c < DV; ++c) ss = fmaf(acc[c], acc[c], ss);
        const float hn = fmaxf(sqrtf(ss), 1e-8f);
        const float scale = tanhf(hn) / hn;

        float4* op = reinterpret_cast<float4*>(out + ((size_t)b * TLEN + i) * DV);
        #pragma unroll
        for (int c4 = 0; c4 < DV / 4; ++c4)
            op[c4] = make_float4(acc[4*c4+0]*scale, acc[4*c4+1]*scale,
                                 acc[4*c4+2]*scale, acc[4*c4+3]*scale);
    }
}

extern "C" void kernel_launch(void* const* d_in, const int* in_sizes, int n_in,
                              void* d_out, int out_size)
{
    const float* q   = (const float*)d_in[0];
    const float* k   = (const float*)d_in[1];
    const float* v   = (const float*)d_in[2];
    const float* s_r = (const float*)d_in[3];
    const float* s_w = (const float*)d_in[4];
    float* out = (float*)d_out;

    // sig(160) + K(288*20) + V(288*68) + list(256*11) floats = ~113.3 KB
    const size_t smem = (size_t)(WIN + KW * KS + KW * VS + NTHREADS * LSTRIDE) * sizeof(float);
    cudaFuncSetAttribute(screening_kernel, cudaFuncAttributeMaxDynamicSharedMemorySize, (int)smem);

    dim3 grid(TLEN / TQ, BATCH);
    screening_kernel<<<grid, NTHREADS, smem>>>(q, k, v, s_r, s_w, out);
}